// round 9
// baseline (speedup 1.0000x reference)
#include <cuda_runtime.h>
#include <cuda_bf16.h>
#include <cstdint>

typedef unsigned long long ull;

#define H 256
#define S 200
#define BSZ 1024
#define BT 8
#define NITEMS 50000
#define KC 32                 // k-pair slabs of W1/W2 cached persistently in smem
#define CHUNK_ULL 3072        // 24 KB chunk = 3072 ull
#define CHUNK_BYTES 24576

// ---------------- device globals ----------------
__device__ ull   g_WhhP[128 * 768];          // packed (k,k+1) pairs, kp-major
__device__ ull   g_W1P[128 * 256];
__device__ ull   g_W2P[128 * 256];
__device__ float g_Etab[(size_t)NITEMS * 768];  // item_emb @ W_ih^T + b_ih
__device__ float g_hfin[BSZ * H];

// ---------------- helpers ----------------
__device__ __forceinline__ void ffma2(ull& d, ull a, ull b) {
    asm("fma.rn.f32x2 %0, %1, %2, %3;" : "=l"(d) : "l"(a), "l"(b), "l"(d));
}
__device__ __forceinline__ ull pack2(float lo, float hi) {
    ull r; asm("mov.b64 %0, {%1, %2};" : "=l"(r) : "f"(lo), "f"(hi)); return r;
}
__device__ __forceinline__ void unpack2(ull v, float& lo, float& hi) {
    asm("mov.b64 {%0, %1}, %2;" : "=f"(lo), "=f"(hi) : "l"(v));
}
__device__ __forceinline__ float hsum2(ull v) {
    float lo, hi; unpack2(v, lo, hi); return lo + hi;
}
__device__ __forceinline__ float sigm(float v) { return 1.0f / (1.0f + __expf(-v)); }
__device__ __forceinline__ float ftanh(float v) {
    float e = __expf(2.0f * v);
    return 1.0f - 2.0f / (e + 1.0f);
}

__device__ __forceinline__ void cp16(uint32_t dst, const ull* src) {
    asm volatile("cp.async.cg.shared.global [%0], [%1], 16;" :: "r"(dst), "l"(src) : "memory");
}
__device__ __forceinline__ void cp_commit() { asm volatile("cp.async.commit_group;" ::: "memory"); }
__device__ __forceinline__ void cp_wait0()  { asm volatile("cp.async.wait_group 0;" ::: "memory"); }

// copy one 24KB chunk (1536 16B units) cooperatively; 3 units per thread
__device__ __forceinline__ void copy_chunk(uint32_t dst_base, const ull* src_base, int tid) {
#pragma unroll
    for (int i = 0; i < 3; i++) {
        int u = tid + i * 512;
        cp16(dst_base + u * 16, src_base + 2 * u);
    }
}

// ---------------- weight packing ----------------
__global__ void prep_pack(const float* __restrict__ W_hh,
                          const float* __restrict__ W1,
                          const float* __restrict__ W2)
{
    int i = blockIdx.x * blockDim.x + threadIdx.x;
    if (i < 128 * 768) {
        int kp = i / 768, m = i % 768;
        g_WhhP[i] = pack2(W_hh[m * H + 2 * kp], W_hh[m * H + 2 * kp + 1]);
    }
    if (i < 128 * 256) {
        int kp = i / 256, jo = i % 256;
        g_W1P[i] = pack2(W1[jo * H + 2 * kp], W1[jo * H + 2 * kp + 1]);
        g_W2P[i] = pack2(W2[jo * H + 2 * kp], W2[jo * H + 2 * kp + 1]);
    }
}

// ---------------- generic C[M,N] = A[M,256] @ B[N,256]^T + bias ----------------
#define GM 64
#define GN 128

__global__ void __launch_bounds__(256) gemm_nt(
    const float* __restrict__ A, const float* __restrict__ B,
    const float* __restrict__ bias, float* __restrict__ C,
    int M, int N)
{
    __shared__ float shA[GM][H];     // 64 KB
    __shared__ float shW[8][132];

    const int n0 = blockIdx.x * GN;
    const int m0 = blockIdx.y * GM;
    const int tid = threadIdx.x;

#pragma unroll
    for (int i = 0; i < 16; i++) {
        int idx = tid + i * 256;
        int r = idx >> 6, c4 = idx & 63;
        int m = m0 + r;
        float4 v = make_float4(0.f, 0.f, 0.f, 0.f);
        if (m < M) v = *(const float4*)&A[(size_t)m * H + c4 * 4];
        *(float4*)&shA[r][c4 * 4] = v;
    }

    const int tn = tid & 31;
    const int tb = tid >> 5;
    const int nl0 = tn * 4;

    ull acc[8][2];
#pragma unroll
    for (int bb = 0; bb < 8; bb++) { acc[bb][0] = 0ull; acc[bb][1] = 0ull; }

    __syncthreads();

    for (int k0 = 0; k0 < H; k0 += 8) {
#pragma unroll
        for (int i = 0; i < 4; i++) {
            int idx = tid + i * 256;
            int nl = idx >> 3, kc = idx & 7;
            int n = n0 + nl;
            shW[kc][nl] = (n < N) ? B[(size_t)n * H + k0 + kc] : 0.f;
        }
        __syncthreads();
#pragma unroll
        for (int kc = 0; kc < 8; kc++) {
            ulonglong2 wv = *(const ulonglong2*)&shW[kc][nl0];
#pragma unroll
            for (int bb = 0; bb < 8; bb++) {
                float hb = shA[tb * 8 + bb][k0 + kc];
                ull hp = pack2(hb, hb);
                ffma2(acc[bb][0], hp, wv.x);
                ffma2(acc[bb][1], hp, wv.y);
            }
        }
        __syncthreads();
    }

    const int nbase = n0 + nl0;
#pragma unroll
    for (int bb = 0; bb < 8; bb++) {
        int m = m0 + tb * 8 + bb;
        if (m >= M) continue;
        float o0, o1, o2, o3;
        unpack2(acc[bb][0], o0, o1);
        unpack2(acc[bb][1], o2, o3);
        if (nbase + 3 < N) {
            float4 o;
            o.x = o0 + bias[nbase + 0];
            o.y = o1 + bias[nbase + 1];
            o.z = o2 + bias[nbase + 2];
            o.w = o3 + bias[nbase + 3];
            *(float4*)&C[(size_t)m * N + nbase] = o;
        } else {
            float ov[4] = {o0, o1, o2, o3};
#pragma unroll
            for (int nn = 0; nn < 4; nn++) {
                int n = nbase + nn;
                if (n < N) C[(size_t)m * N + n] = ov[nn] + bias[n];
            }
        }
    }
}

// ---------------- ODE layer matmul: cached KC slabs + streamed 96 kp ----------------
// half h owns: cached kp [16h,16h+16) ; per streamed chunk c (12 kp), kp [KC+12c+6h, +6)
__device__ __forceinline__ void mm_layer(const float (*__restrict__ src)[H],
                                         const ull* __restrict__ sWc,
                                         const ull* __restrict__ gW,
                                         const ull* __restrict__ buf, uint32_t bufs,
                                         int j, int half, int tid, ull* acc)
{
    // issue chunk 0 (hidden behind cached compute)
    copy_chunk(bufs, gW + KC * H, tid);
    cp_commit();

#pragma unroll
    for (int r = 0; r < BT; r++) acc[r] = 0ull;

    // cached 16 kp for this half
    const int kc0 = 16 * half;
#pragma unroll 2
    for (int p = 0; p < 8; p++) {
        int kp = kc0 + 2 * p;
        ull w0 = sWc[kp * H + j];
        ull w1 = sWc[(kp + 1) * H + j];
#pragma unroll
        for (int r = 0; r < BT; r++) {
            ulonglong2 sv = *(const ulonglong2*)&src[r][2 * kp];
            ffma2(acc[r], sv.x, w0);
            ffma2(acc[r], sv.y, w1);
        }
    }

    // streamed: 8 chunks x 12 kp (6 per half)
#pragma unroll 1
    for (int c = 0; c < 8; c++) {
        cp_wait0();
        __syncthreads();
        if (c < 7) {
            copy_chunk(bufs + ((c + 1) & 1) * CHUNK_BYTES, gW + (size_t)(KC + 12 * (c + 1)) * H, tid);
            cp_commit();
        }
        const ull* wb = buf + (c & 1) * CHUNK_ULL + (6 * half) * H + j;
        const int kb = KC + 12 * c + 6 * half;
#pragma unroll
        for (int p = 0; p < 3; p++) {
            ull w0 = wb[(2 * p) * H];
            ull w1 = wb[(2 * p + 1) * H];
#pragma unroll
            for (int r = 0; r < BT; r++) {
                ulonglong2 sv = *(const ulonglong2*)&src[r][2 * (kb + 2 * p)];
                ffma2(acc[r], sv.x, w0);
                ffma2(acc[r], sv.y, w1);
            }
        }
    }
}

// ---------------- recurrent kernel: 512 threads, K split, cp.async streaming ----------------
__global__ void __launch_bounds__(512) rec_kernel(
    const int* __restrict__ x, const float* __restrict__ tt,
    const float* __restrict__ b_hh,
    const float* __restrict__ b1, const float* __restrict__ b2)
{
    extern __shared__ ull dynsmem[];
    ull* sW1 = dynsmem;                          // KC*H ull (64 KB)
    ull* sW2 = sW1 + KC * H;                     // 64 KB
    ull* buf = sW2 + KC * H;                     // 2 x CHUNK_ULL (48 KB)
    float* fbase = (float*)(buf + 2 * CHUNK_ULL);
    float (*sh_h)[H] = (float (*)[H])fbase;                  // 8 KB
    float (*sh_a)[H] = (float (*)[H])(fbase + BT * H);       // 8 KB
    float (*sh_t)[H] = (float (*)[H])(fbase + 2 * BT * H);   // 8 KB
    float* red = fbase + 3 * BT * H;                         // 6144 f (24 KB)
    int*   sh_it = (int*)(red + 2 * 3 * 4 * H);
    float* sh_dt = (float*)(sh_it + BT);

    const int tid = threadIdx.x;
    const int j = tid & 255;
    const int half = tid >> 8;
    const int r0 = half * 4;
    const int b0 = blockIdx.x * BT;
    const uint32_t bufs = (uint32_t)__cvta_generic_to_shared(buf);

#define RG(hh, g, q) ((((hh) * 3 + (g)) * 4 + (q)) * H + j)

    // persistent W1/W2 cache
    for (int i = tid; i < KC * H; i += 512) { sW1[i] = g_W1P[i]; sW2[i] = g_W2P[i]; }

    const float bhhr = b_hh[j], bhhz = b_hh[H + j], bhhn = b_hh[2 * H + j];
    const float b1j = b1[j], b2j = b2[j];

#pragma unroll
    for (int q = 0; q < 4; q++) sh_h[r0 + q][j] = 0.f;
    float hnew[4];
#pragma unroll
    for (int q = 0; q < 4; q++) hnew[q] = 0.f;
    __syncthreads();

    const ull* __restrict__ whh = g_WhhP;

    for (int s = 0; s < S; s++) {
        // step inputs (8 threads)
        if (tid < BT) {
            sh_it[tid] = x[(b0 + tid) * S + s];
            float tc = tt[(b0 + tid) * S + s];
            float d = 0.f;
            if (s < S - 1) {
                float tn = tt[(b0 + tid) * S + s + 1];
                d = fmaxf(tn, tc + 1e-5f) - tc;
            }
            sh_dt[tid] = d;
        }

        // ---- GRU: stream W_hh in 32 chunks of 4 kp (2 per half) ----
        copy_chunk(bufs, whh, tid);                   // chunk 0
        cp_commit();
        cp_wait0();
        __syncthreads();                              // chunk0 + sh_it/sh_dt visible
        copy_chunk(bufs + CHUNK_BYTES, whh + (size_t)4 * 768, tid);   // chunk 1
        cp_commit();

        // issue long-latency Etab gathers now (consumed after GRU matmul)
        float giR[4], giZ[4], giN[4], dt4[4];
#pragma unroll
        for (int q = 0; q < 4; q++) {
            const float* e = g_Etab + (size_t)sh_it[r0 + q] * 768;
            giR[q] = e[j];
            giZ[q] = e[H + j];
            giN[q] = e[2 * H + j];
            dt4[q] = sh_dt[r0 + q];
        }

        ull aR[BT], aZ[BT], aN[BT];
#pragma unroll
        for (int r = 0; r < BT; r++) { aR[r] = 0ull; aZ[r] = 0ull; aN[r] = 0ull; }

        // compute chunk 0
        {
            const ull* wb = buf + (2 * half) * 768 + j;
            ull w0R = wb[0],   w0Z = wb[256],  w0N = wb[512];
            ull w1R = wb[768], w1Z = wb[1024], w1N = wb[1280];
            const int kg = 2 * half;
#pragma unroll
            for (int r = 0; r < BT; r++) {
                ulonglong2 hv = *(const ulonglong2*)&sh_h[r][2 * kg];
                ffma2(aR[r], hv.x, w0R);
                ffma2(aZ[r], hv.x, w0Z);
                ffma2(aN[r], hv.x, w0N);
                ffma2(aR[r], hv.y, w1R);
                ffma2(aZ[r], hv.y, w1Z);
                ffma2(aN[r], hv.y, w1N);
            }
        }

#pragma unroll 1
        for (int c = 1; c < 32; c++) {
            cp_wait0();
            __syncthreads();
            if (c < 31) {
                copy_chunk(bufs + ((c + 1) & 1) * CHUNK_BYTES, whh + (size_t)4 * (c + 1) * 768, tid);
                cp_commit();
            }
            const ull* wb = buf + (c & 1) * CHUNK_ULL + (2 * half) * 768 + j;
            ull w0R = wb[0],   w0Z = wb[256],  w0N = wb[512];
            ull w1R = wb[768], w1Z = wb[1024], w1N = wb[1280];
            const int kg = 4 * c + 2 * half;
#pragma unroll
            for (int r = 0; r < BT; r++) {
                ulonglong2 hv = *(const ulonglong2*)&sh_h[r][2 * kg];
                ffma2(aR[r], hv.x, w0R);
                ffma2(aZ[r], hv.x, w0Z);
                ffma2(aN[r], hv.x, w0N);
                ffma2(aR[r], hv.y, w1R);
                ffma2(aZ[r], hv.y, w1Z);
                ffma2(aN[r], hv.y, w1N);
            }
        }

        // partials for the OTHER half's rows
        {
            const int ro = (1 - half) * 4;
#pragma unroll
            for (int q = 0; q < 4; q++) {
                red[RG(half, 0, q)] = hsum2(aR[ro + q]);
                red[RG(half, 1, q)] = hsum2(aZ[ro + q]);
                red[RG(half, 2, q)] = hsum2(aN[ro + q]);
            }
        }
        __syncthreads();

        // combine + GRU elementwise (gate order r,z,n)
#pragma unroll
        for (int q = 0; q < 4; q++) {
            int r = r0 + q;
            float pR = hsum2(aR[r]) + red[RG(1 - half, 0, q)];
            float pZ = hsum2(aZ[r]) + red[RG(1 - half, 1, q)];
            float pN = hsum2(aN[r]) + red[RG(1 - half, 2, q)];
            float rg = sigm(giR[q] + pR + bhhr);
            float zg = sigm(giZ[q] + pZ + bhhz);
            float ng = ftanh(giN[q] + rg * (pN + bhhn));
            float hold = sh_h[r][j];
            hnew[q] = (1.f - zg) * ng + zg * hold;
        }
        __syncthreads();
#pragma unroll
        for (int q = 0; q < 4; q++) sh_h[r0 + q][j] = hnew[q];
        __syncthreads();

        // ---- RK4 ----
        float ksum[4], kv[4];
        ull acc[BT];
        float (*src)[H] = sh_h;

#pragma unroll 1
        for (int eval = 0; eval < 4; eval++) {
            // layer 1
            mm_layer(src, sW1, g_W1P, buf, bufs, j, half, tid, acc);
            {
                const int ro = (1 - half) * 4;
#pragma unroll
                for (int q = 0; q < 4; q++) red[RG(half, 0, q)] = hsum2(acc[ro + q]);
            }
            __syncthreads();
#pragma unroll
            for (int q = 0; q < 4; q++) {
                int r = r0 + q;
                sh_a[r][j] = ftanh(hsum2(acc[r]) + red[RG(1 - half, 0, q)] + b1j);
            }
            __syncthreads();

            // layer 2
            mm_layer(sh_a, sW2, g_W2P, buf, bufs, j, half, tid, acc);
            {
                const int ro = (1 - half) * 4;
#pragma unroll
                for (int q = 0; q < 4; q++) red[RG(half, 0, q)] = hsum2(acc[ro + q]);
            }
            __syncthreads();
#pragma unroll
            for (int q = 0; q < 4; q++) {
                kv[q] = hsum2(acc[r0 + q]) + red[RG(1 - half, 0, q)] + b2j;
            }

            if (eval == 0) {
#pragma unroll
                for (int q = 0; q < 4; q++) {
                    ksum[q] = kv[q];
                    sh_t[r0 + q][j] = hnew[q] + 0.5f * dt4[q] * kv[q];
                }
            } else if (eval == 1) {
#pragma unroll
                for (int q = 0; q < 4; q++) {
                    ksum[q] += 2.f * kv[q];
                    sh_t[r0 + q][j] = hnew[q] + 0.5f * dt4[q] * kv[q];
                }
            } else if (eval == 2) {
#pragma unroll
                for (int q = 0; q < 4; q++) {
                    ksum[q] += 2.f * kv[q];
                    sh_t[r0 + q][j] = hnew[q] + dt4[q] * kv[q];
                }
            } else {
#pragma unroll
                for (int q = 0; q < 4; q++) {
                    ksum[q] += kv[q];
                    hnew[q] = hnew[q] + (dt4[q] * (1.f / 6.f)) * ksum[q];
                    sh_h[r0 + q][j] = hnew[q];
                }
            }
            __syncthreads();
            src = sh_t;
        }
    }

#pragma unroll
    for (int q = 0; q < 4; q++) g_hfin[(b0 + r0 + q) * H + j] = hnew[q];
#undef RG
}

// ---------------- launch ----------------
extern "C" void kernel_launch(void* const* d_in, const int* in_sizes, int n_in,
                              void* d_out, int out_size)
{
    const int*   x      = (const int*)d_in[0];
    const float* t      = (const float*)d_in[1];
    const float* emb    = (const float*)d_in[2];
    const float* W_ih   = (const float*)d_in[3];
    const float* W_hh   = (const float*)d_in[4];
    const float* b_ih   = (const float*)d_in[5];
    const float* b_hh   = (const float*)d_in[6];
    const float* W1     = (const float*)d_in[7];
    const float* b1     = (const float*)d_in[8];
    const float* W2     = (const float*)d_in[9];
    const float* b2     = (const float*)d_in[10];
    const float* W_head = (const float*)d_in[11];
    const float* b_head = (const float*)d_in[12];
    float* out = (float*)d_out;

    float* etab_ptr = nullptr;
    float* hfin_ptr = nullptr;
    cudaGetSymbolAddress((void**)&etab_ptr, g_Etab);
    cudaGetSymbolAddress((void**)&hfin_ptr, g_hfin);

    const int smem_bytes = 2 * KC * H * (int)sizeof(ull)      // W1/W2 persistent cache (128 KB)
                         + 2 * CHUNK_BYTES                     // stream double-buffer (48 KB)
                         + 3 * BT * H * (int)sizeof(float)     // h/a/t (24 KB)
                         + 2 * 3 * 4 * H * (int)sizeof(float)  // reduction buffer (24 KB)
                         + BT * (int)(sizeof(int) + sizeof(float));
    cudaFuncSetAttribute(rec_kernel, cudaFuncAttributeMaxDynamicSharedMemorySize, smem_bytes);

    prep_pack<<<(128 * 768 + 255) / 256, 256>>>(W_hh, W1, W2);

    // Etab = item_emb @ W_ih^T + b_ih   [50000, 768]
    dim3 ge(768 / GN, (NITEMS + GM - 1) / GM);
    gemm_nt<<<ge, 256>>>(emb, W_ih, b_ih, etab_ptr, NITEMS, 768);

    rec_kernel<<<BSZ / BT, 512, smem_bytes>>>(x, t, b_hh, b1, b2);

    // out = h_fin @ W_head^T + b_head   [1024, 50000]
    dim3 gh((NITEMS + GN - 1) / GN, BSZ / GM);
    gemm_nt<<<gh, 256>>>(hfin_ptr, W_head, b_head, out, BSZ, NITEMS);
}

// round 10
// speedup vs baseline: 1.1438x; 1.1438x over previous
#include <cuda_runtime.h>
#include <cuda_bf16.h>
#include <cstdint>

typedef unsigned long long ull;

#define H 256
#define S 200
#define BSZ 1024
#define BT 8
#define NITEMS 50000
#define KC 40            // k-pair slabs of W1/W2 cached in smem (of 128)

// ---------------- device globals ----------------
__device__ ull   g_WhhP[128 * 768];          // packed (k,k+1) pairs, kp-major
__device__ ull   g_W1P[128 * 256];
__device__ ull   g_W2P[128 * 256];
__device__ float g_Etab[(size_t)NITEMS * 768];  // item_emb @ W_ih^T + b_ih
__device__ float g_hfin[BSZ * H];

// ---------------- helpers ----------------
__device__ __forceinline__ void ffma2(ull& d, ull a, ull b) {
    asm("fma.rn.f32x2 %0, %1, %2, %3;" : "=l"(d) : "l"(a), "l"(b), "l"(d));
}
__device__ __forceinline__ ull pack2(float lo, float hi) {
    ull r; asm("mov.b64 %0, {%1, %2};" : "=l"(r) : "f"(lo), "f"(hi)); return r;
}
__device__ __forceinline__ void unpack2(ull v, float& lo, float& hi) {
    asm("mov.b64 {%0, %1}, %2;" : "=f"(lo), "=f"(hi) : "l"(v));
}
__device__ __forceinline__ float hsum2(ull v) {
    float lo, hi; unpack2(v, lo, hi); return lo + hi;
}
__device__ __forceinline__ float sigm(float v) { return 1.0f / (1.0f + __expf(-v)); }
__device__ __forceinline__ float ftanh(float v) {
    float e = __expf(2.0f * v);
    return 1.0f - 2.0f / (e + 1.0f);
}

// ---------------- weight packing ----------------
__global__ void prep_pack(const float* __restrict__ W_hh,
                          const float* __restrict__ W1,
                          const float* __restrict__ W2)
{
    int i = blockIdx.x * blockDim.x + threadIdx.x;
    if (i < 128 * 768) {
        int kp = i / 768, m = i % 768;
        g_WhhP[i] = pack2(W_hh[m * H + 2 * kp], W_hh[m * H + 2 * kp + 1]);
    }
    if (i < 128 * 256) {
        int kp = i / 256, jo = i % 256;
        g_W1P[i] = pack2(W1[jo * H + 2 * kp], W1[jo * H + 2 * kp + 1]);
        g_W2P[i] = pack2(W2[jo * H + 2 * kp], W2[jo * H + 2 * kp + 1]);
    }
}

// ---------------- generic C[M,N] = A[M,256] @ B[N,256]^T + bias ----------------
#define GM 64
#define GN 128

__global__ void __launch_bounds__(256) gemm_nt(
    const float* __restrict__ A, const float* __restrict__ B,
    const float* __restrict__ bias, float* __restrict__ C,
    int M, int N)
{
    __shared__ float shA[GM][H];     // 64 KB
    __shared__ float shW[8][132];

    const int n0 = blockIdx.x * GN;
    const int m0 = blockIdx.y * GM;
    const int tid = threadIdx.x;

#pragma unroll
    for (int i = 0; i < 16; i++) {
        int idx = tid + i * 256;
        int r = idx >> 6, c4 = idx & 63;
        int m = m0 + r;
        float4 v = make_float4(0.f, 0.f, 0.f, 0.f);
        if (m < M) v = *(const float4*)&A[(size_t)m * H + c4 * 4];
        *(float4*)&shA[r][c4 * 4] = v;
    }

    const int tn = tid & 31;
    const int tb = tid >> 5;
    const int nl0 = tn * 4;

    ull acc[8][2];
#pragma unroll
    for (int bb = 0; bb < 8; bb++) { acc[bb][0] = 0ull; acc[bb][1] = 0ull; }

    __syncthreads();

    for (int k0 = 0; k0 < H; k0 += 8) {
#pragma unroll
        for (int i = 0; i < 4; i++) {
            int idx = tid + i * 256;
            int nl = idx >> 3, kc = idx & 7;
            int n = n0 + nl;
            shW[kc][nl] = (n < N) ? B[(size_t)n * H + k0 + kc] : 0.f;
        }
        __syncthreads();
#pragma unroll
        for (int kc = 0; kc < 8; kc++) {
            ulonglong2 wv = *(const ulonglong2*)&shW[kc][nl0];
#pragma unroll
            for (int bb = 0; bb < 8; bb++) {
                float hb = shA[tb * 8 + bb][k0 + kc];
                ull hp = pack2(hb, hb);
                ffma2(acc[bb][0], hp, wv.x);
                ffma2(acc[bb][1], hp, wv.y);
            }
        }
        __syncthreads();
    }

    const int nbase = n0 + nl0;
#pragma unroll
    for (int bb = 0; bb < 8; bb++) {
        int m = m0 + tb * 8 + bb;
        if (m >= M) continue;
        float o0, o1, o2, o3;
        unpack2(acc[bb][0], o0, o1);
        unpack2(acc[bb][1], o2, o3);
        if (nbase + 3 < N) {
            float4 o;
            o.x = o0 + bias[nbase + 0];
            o.y = o1 + bias[nbase + 1];
            o.z = o2 + bias[nbase + 2];
            o.w = o3 + bias[nbase + 3];
            *(float4*)&C[(size_t)m * N + nbase] = o;
        } else {
            float ov[4] = {o0, o1, o2, o3};
#pragma unroll
            for (int nn = 0; nn < 4; nn++) {
                int n = nbase + nn;
                if (n < N) C[(size_t)m * N + n] = ov[nn] + bias[n];
            }
        }
    }
}

// ---------------- ODE partial matmul: third t's kp range ----------------
// kp pairs: t0: pairs 0..21 (0..19 cached, 20..21 global)
//           t1: pairs 22..43 (global)   t2: pairs 44..63 (global)
__device__ __forceinline__ void mm_third(const float (*__restrict__ src)[H],
                                         const ull* __restrict__ sWc,
                                         const ull* __restrict__ gW,
                                         int j, int t, ull* acc)
{
#pragma unroll
    for (int r = 0; r < BT; r++) acc[r] = 0ull;

    if (t == 0) {
#pragma unroll 2
        for (int p = 0; p < 20; p++) {          // cached kp 0..39
            ull w0 = sWc[(2 * p) * H + j];
            ull w1 = sWc[(2 * p + 1) * H + j];
#pragma unroll
            for (int r = 0; r < BT; r++) {
                ulonglong2 sv = *(const ulonglong2*)&src[r][4 * p];
                ffma2(acc[r], sv.x, w0);
                ffma2(acc[r], sv.y, w1);
            }
        }
#pragma unroll
        for (int p = 20; p < 22; p++) {         // global kp 40..43
            ull w0 = gW[(size_t)(2 * p) * H + j];
            ull w1 = gW[(size_t)(2 * p + 1) * H + j];
#pragma unroll
            for (int r = 0; r < BT; r++) {
                ulonglong2 sv = *(const ulonglong2*)&src[r][4 * p];
                ffma2(acc[r], sv.x, w0);
                ffma2(acc[r], sv.y, w1);
            }
        }
    } else {
        const int pb = (t == 1) ? 22 : 44;
        const int ni = (t == 1) ? 22 : 20;
#pragma unroll 2
        for (int c = 0; c < ni; c++) {
            const int p = pb + c;
            ull w0 = gW[(size_t)(2 * p) * H + j];
            ull w1 = gW[(size_t)(2 * p + 1) * H + j];
#pragma unroll
            for (int r = 0; r < BT; r++) {
                ulonglong2 sv = *(const ulonglong2*)&src[r][4 * p];
                ffma2(acc[r], sv.x, w0);
                ffma2(acc[r], sv.y, w1);
            }
        }
    }
}

// ---------------- recurrent kernel: 768 threads = 256 cols x 3 thirds ----------------
__global__ void __launch_bounds__(768) rec_kernel(
    const int* __restrict__ x, const float* __restrict__ tt,
    const float* __restrict__ b_hh,
    const float* __restrict__ b1, const float* __restrict__ b2)
{
    extern __shared__ ull dynsmem[];
    ull* sW1 = dynsmem;                          // 40*256 ull = 80 KB
    ull* sW2 = sW1 + KC * H;                     // 80 KB
    float* fbase = (float*)(sW2 + KC * H);
    float (*sh_h)[H] = (float (*)[H])fbase;                  // 8 KB
    float (*sh_a)[H] = (float (*)[H])(fbase + BT * H);       // 8 KB
    float (*sh_t)[H] = (float (*)[H])(fbase + 2 * BT * H);   // 8 KB
    float* red = fbase + 3 * BT * H;                         // 3*8*256 f = 24 KB
    int*   sh_it = (int*)(red + 3 * BT * H);
    float* sh_dt = (float*)(sh_it + BT);

    const int tid = threadIdx.x;
    const int j = tid & 255;
    const int t = tid >> 8;                      // 0..2
    const int rbase = t * 3;                     // owned rows
    const int NR = (t == 2) ? 2 : 3;
    const int b0 = blockIdx.x * BT;

#define RED(tt_, r_) ((((tt_) * BT) + (r_)) * H + j)

    for (int i = tid; i < KC * H; i += 768) { sW1[i] = g_W1P[i]; sW2[i] = g_W2P[i]; }

    const float bhh_t = b_hh[t * 256 + j];
    const float b1j = b1[j], b2j = b2[j];

    if (t == 0) {
#pragma unroll
        for (int r = 0; r < BT; r++) sh_h[r][j] = 0.f;
    }
    float hnew_o[3];
#pragma unroll
    for (int q = 0; q < 3; q++) hnew_o[q] = 0.f;
    __syncthreads();

    const ull* __restrict__ whh = g_WhhP;

    for (int s = 0; s < S; s++) {
        if (tid < BT) {
            sh_it[tid] = x[(b0 + tid) * S + s];
            float tc = tt[(b0 + tid) * S + s];
            float d = 0.f;
            if (s < S - 1) {
                float tn = tt[(b0 + tid) * S + s + 1];
                d = fmaxf(tn, tc + 1e-5f) - tc;
            }
            sh_dt[tid] = d;
        }
        __syncthreads();   // (1)

        // Etab gathers: gates r,z only (n-gate i_n loaded by row-owners later)
        float gi[BT];
        if (t < 2) {
#pragma unroll
            for (int r = 0; r < BT; r++)
                gi[r] = g_Etab[(size_t)sh_it[r] * 768 + t * 256 + j];
        }

        float dt_o[3];
#pragma unroll
        for (int q = 0; q < 3; q++)
            if (q < NR) dt_o[q] = sh_dt[rbase + q];

        // ---- GRU matmul: gate t, all 8 rows, full K ----
        {
            ull acc[BT];
#pragma unroll
            for (int r = 0; r < BT; r++) acc[r] = 0ull;
            const ull* wg = whh + t * 256 + j;
#pragma unroll 4
            for (int p = 0; p < 64; p++) {
                ull w0 = wg[(size_t)(2 * p) * 768];
                ull w1 = wg[(size_t)(2 * p + 1) * 768];
#pragma unroll
                for (int r = 0; r < BT; r++) {
                    ulonglong2 hv = *(const ulonglong2*)&sh_h[r][4 * p];
                    ffma2(acc[r], hv.x, w0);
                    ffma2(acc[r], hv.y, w1);
                }
            }
#pragma unroll
            for (int r = 0; r < BT; r++) {
                float v = hsum2(acc[r]) + bhh_t;
                if (t < 2) v += gi[r];
                red[RED(t, r)] = v;
            }
        }
        __syncthreads();   // (2)

        // ---- GRU elementwise for owned rows ----
#pragma unroll
        for (int q = 0; q < 3; q++) {
            if (q >= NR) break;
            int r = rbase + q;
            float i_n = g_Etab[(size_t)sh_it[r] * 768 + 512 + j];
            float rg = sigm(red[RED(0, r)]);
            float zg = sigm(red[RED(1, r)]);
            float ng = ftanh(i_n + rg * red[RED(2, r)]);
            float hold = sh_h[r][j];
            hnew_o[q] = (1.f - zg) * ng + zg * hold;
            sh_h[r][j] = hnew_o[q];
        }
        __syncthreads();   // (3)

        // ---- RK4 ----
        float ksum[3], kv[3];
        ull acc[BT];
        float (*src)[H] = sh_h;

#pragma unroll 1
        for (int eval = 0; eval < 4; eval++) {
            mm_third(src, sW1, g_W1P, j, t, acc);
#pragma unroll
            for (int r = 0; r < BT; r++) red[RED(t, r)] = hsum2(acc[r]);
            __syncthreads();

#pragma unroll
            for (int q = 0; q < 3; q++) {
                if (q >= NR) break;
                int r = rbase + q;
                float v = red[RED(0, r)] + red[RED(1, r)] + red[RED(2, r)] + b1j;
                sh_a[r][j] = ftanh(v);
            }
            __syncthreads();

            mm_third(sh_a, sW2, g_W2P, j, t, acc);
#pragma unroll
            for (int r = 0; r < BT; r++) red[RED(t, r)] = hsum2(acc[r]);
            __syncthreads();

#pragma unroll
            for (int q = 0; q < 3; q++) {
                if (q >= NR) break;
                int r = rbase + q;
                kv[q] = red[RED(0, r)] + red[RED(1, r)] + red[RED(2, r)] + b2j;
            }
            if (eval == 0) {
#pragma unroll
                for (int q = 0; q < 3; q++) {
                    if (q >= NR) break;
                    ksum[q] = kv[q];
                    sh_t[rbase + q][j] = hnew_o[q] + 0.5f * dt_o[q] * kv[q];
                }
            } else if (eval == 1) {
#pragma unroll
                for (int q = 0; q < 3; q++) {
                    if (q >= NR) break;
                    ksum[q] += 2.f * kv[q];
                    sh_t[rbase + q][j] = hnew_o[q] + 0.5f * dt_o[q] * kv[q];
                }
            } else if (eval == 2) {
#pragma unroll
                for (int q = 0; q < 3; q++) {
                    if (q >= NR) break;
                    ksum[q] += 2.f * kv[q];
                    sh_t[rbase + q][j] = hnew_o[q] + dt_o[q] * kv[q];
                }
            } else {
#pragma unroll
                for (int q = 0; q < 3; q++) {
                    if (q >= NR) break;
                    ksum[q] += kv[q];
                    hnew_o[q] = hnew_o[q] + (dt_o[q] * (1.f / 6.f)) * ksum[q];
                    sh_h[rbase + q][j] = hnew_o[q];
                }
            }
            __syncthreads();
            src = sh_t;
        }
    }

#pragma unroll
    for (int q = 0; q < 3; q++) {
        if (q >= NR) break;
        g_hfin[(b0 + rbase + q) * H + j] = hnew_o[q];
    }
#undef RED
}

// ---------------- launch ----------------
extern "C" void kernel_launch(void* const* d_in, const int* in_sizes, int n_in,
                              void* d_out, int out_size)
{
    const int*   x      = (const int*)d_in[0];
    const float* t      = (const float*)d_in[1];
    const float* emb    = (const float*)d_in[2];
    const float* W_ih   = (const float*)d_in[3];
    const float* W_hh   = (const float*)d_in[4];
    const float* b_ih   = (const float*)d_in[5];
    const float* b_hh   = (const float*)d_in[6];
    const float* W1     = (const float*)d_in[7];
    const float* b1     = (const float*)d_in[8];
    const float* W2     = (const float*)d_in[9];
    const float* b2     = (const float*)d_in[10];
    const float* W_head = (const float*)d_in[11];
    const float* b_head = (const float*)d_in[12];
    float* out = (float*)d_out;

    float* etab_ptr = nullptr;
    float* hfin_ptr = nullptr;
    cudaGetSymbolAddress((void**)&etab_ptr, g_Etab);
    cudaGetSymbolAddress((void**)&hfin_ptr, g_hfin);

    const int smem_bytes = 2 * KC * H * (int)sizeof(ull)
                         + 3 * BT * H * (int)sizeof(float)
                         + 3 * BT * H * (int)sizeof(float)
                         + BT * (int)(sizeof(int) + sizeof(float));
    cudaFuncSetAttribute(rec_kernel, cudaFuncAttributeMaxDynamicSharedMemorySize, smem_bytes);

    prep_pack<<<(128 * 768 + 255) / 256, 256>>>(W_hh, W1, W2);

    dim3 ge(768 / GN, (NITEMS + GM - 1) / GM);
    gemm_nt<<<ge, 256>>>(emb, W_ih, b_ih, etab_ptr, NITEMS, 768);

    rec_kernel<<<BSZ / BT, 768, smem_bytes>>>(x, t, b_hh, b1, b2);

    dim3 gh((NITEMS + GN - 1) / GN, BSZ / GM);
    gemm_nt<<<gh, 256>>>(hfin_ptr, W_head, b_head, out, BSZ, NITEMS);
}

// round 11
// speedup vs baseline: 1.3561x; 1.1856x over previous
#include <cuda_runtime.h>
#include <cuda_fp16.h>
#include <cstdint>

typedef unsigned long long ull;

#define H 256
#define S 200
#define BSZ 1024
#define BT 8
#define NITEMS 50000
#define KC 72                 // k-pair slabs of W1/W2 cached in smem (of 128), fp16
#define KCH (KC / 2)          // 36 cached kp per half
#define GKPH ((128 - KC) / 2) // 28 global kp per half

// ---------------- device globals ----------------
__device__ ull     g_WhhP[128 * 768];           // fp32 packed (k,k+1) pairs, kp-major
__device__ __half2 g_W1H[128 * 256];            // fp16 pairs, kp-major
__device__ __half2 g_W2H[128 * 256];
__device__ float   g_Etab[(size_t)NITEMS * 768];
__device__ float   g_hfin[BSZ * H];

// ---------------- helpers ----------------
__device__ __forceinline__ void ffma2(ull& d, ull a, ull b) {
    asm("fma.rn.f32x2 %0, %1, %2, %3;" : "=l"(d) : "l"(a), "l"(b), "l"(d));
}
__device__ __forceinline__ ull pack2(float lo, float hi) {
    ull r; asm("mov.b64 %0, {%1, %2};" : "=l"(r) : "f"(lo), "f"(hi)); return r;
}
__device__ __forceinline__ void unpack2(ull v, float& lo, float& hi) {
    asm("mov.b64 {%0, %1}, %2;" : "=f"(lo), "=f"(hi) : "l"(v));
}
__device__ __forceinline__ float hsum2(ull v) {
    float lo, hi; unpack2(v, lo, hi); return lo + hi;
}
__device__ __forceinline__ ull h2ull(__half2 h) {
    float2 f = __half22float2(h);
    return pack2(f.x, f.y);
}
__device__ __forceinline__ float sigm(float v) { return 1.0f / (1.0f + __expf(-v)); }
__device__ __forceinline__ float ftanh(float v) {
    float e = __expf(2.0f * v);
    return 1.0f - 2.0f / (e + 1.0f);
}

// ---------------- weight packing ----------------
__global__ void prep_pack(const float* __restrict__ W_hh,
                          const float* __restrict__ W1,
                          const float* __restrict__ W2)
{
    int i = blockIdx.x * blockDim.x + threadIdx.x;
    if (i < 128 * 768) {
        int kp = i / 768, m = i % 768;
        g_WhhP[i] = pack2(W_hh[m * H + 2 * kp], W_hh[m * H + 2 * kp + 1]);
    }
    if (i < 128 * 256) {
        int kp = i / 256, jo = i % 256;
        g_W1H[i] = __floats2half2_rn(W1[jo * H + 2 * kp], W1[jo * H + 2 * kp + 1]);
        g_W2H[i] = __floats2half2_rn(W2[jo * H + 2 * kp], W2[jo * H + 2 * kp + 1]);
    }
}

// ---------------- generic C[M,N] = A[M,256] @ B[N,256]^T + bias ----------------
#define GM 64
#define GN 128

__global__ void __launch_bounds__(256) gemm_nt(
    const float* __restrict__ A, const float* __restrict__ B,
    const float* __restrict__ bias, float* __restrict__ C,
    int M, int N)
{
    __shared__ float shA[GM][H];     // 64 KB
    __shared__ float shW[8][132];

    const int n0 = blockIdx.x * GN;
    const int m0 = blockIdx.y * GM;
    const int tid = threadIdx.x;

#pragma unroll
    for (int i = 0; i < 16; i++) {
        int idx = tid + i * 256;
        int r = idx >> 6, c4 = idx & 63;
        int m = m0 + r;
        float4 v = make_float4(0.f, 0.f, 0.f, 0.f);
        if (m < M) v = *(const float4*)&A[(size_t)m * H + c4 * 4];
        *(float4*)&shA[r][c4 * 4] = v;
    }

    const int tn = tid & 31;
    const int tb = tid >> 5;
    const int nl0 = tn * 4;

    ull acc[8][2];
#pragma unroll
    for (int bb = 0; bb < 8; bb++) { acc[bb][0] = 0ull; acc[bb][1] = 0ull; }

    __syncthreads();

    for (int k0 = 0; k0 < H; k0 += 8) {
#pragma unroll
        for (int i = 0; i < 4; i++) {
            int idx = tid + i * 256;
            int nl = idx >> 3, kc = idx & 7;
            int n = n0 + nl;
            shW[kc][nl] = (n < N) ? B[(size_t)n * H + k0 + kc] : 0.f;
        }
        __syncthreads();
#pragma unroll
        for (int kc = 0; kc < 8; kc++) {
            ulonglong2 wv = *(const ulonglong2*)&shW[kc][nl0];
#pragma unroll
            for (int bb = 0; bb < 8; bb++) {
                float hb = shA[tb * 8 + bb][k0 + kc];
                ull hp = pack2(hb, hb);
                ffma2(acc[bb][0], hp, wv.x);
                ffma2(acc[bb][1], hp, wv.y);
            }
        }
        __syncthreads();
    }

    const int nbase = n0 + nl0;
#pragma unroll
    for (int bb = 0; bb < 8; bb++) {
        int m = m0 + tb * 8 + bb;
        if (m >= M) continue;
        float o0, o1, o2, o3;
        unpack2(acc[bb][0], o0, o1);
        unpack2(acc[bb][1], o2, o3);
        if (nbase + 3 < N) {
            float4 o;
            o.x = o0 + bias[nbase + 0];
            o.y = o1 + bias[nbase + 1];
            o.z = o2 + bias[nbase + 2];
            o.w = o3 + bias[nbase + 3];
            *(float4*)&C[(size_t)m * N + nbase] = o;
        } else {
            float ov[4] = {o0, o1, o2, o3};
#pragma unroll
            for (int nn = 0; nn < 4; nn++) {
                int n = nbase + nn;
                if (n < N) C[(size_t)m * N + n] = ov[nn] + bias[n];
            }
        }
    }
}

// ---------------- ODE partial matmul over this half's kp range (fp16 weights) ----------------
__device__ __forceinline__ void mm_partial(const float (*__restrict__ src)[H],
                                           const __half2* __restrict__ ws,  // smem, abs kp<KC
                                           const __half2* __restrict__ wg,  // global, full
                                           int j, int half, ull* acc)
{
#pragma unroll
    for (int r = 0; r < BT; r++) acc[r] = 0ull;

    // cached: KCH=36 kp per half
    const int kc0 = half * KCH;
#pragma unroll 2
    for (int c = 0; c < KCH / 2; c++) {
        int kp = kc0 + 2 * c;
        ull w0 = h2ull(ws[kp * H + j]);
        ull w1 = h2ull(ws[(kp + 1) * H + j]);
#pragma unroll
        for (int r = 0; r < BT; r++) {
            ulonglong2 sv = *(const ulonglong2*)&src[r][2 * kp];
            ffma2(acc[r], sv.x, w0);
            ffma2(acc[r], sv.y, w1);
        }
    }

    // global: GKPH=28 kp per half
    const int kg0 = KC + half * GKPH;
#pragma unroll 2
    for (int c = 0; c < GKPH / 2; c++) {
        int kp = kg0 + 2 * c;
        ull w0 = h2ull(wg[(size_t)kp * H + j]);
        ull w1 = h2ull(wg[(size_t)(kp + 1) * H + j]);
#pragma unroll
        for (int r = 0; r < BT; r++) {
            ulonglong2 sv = *(const ulonglong2*)&src[r][2 * kp];
            ffma2(acc[r], sv.x, w0);
            ffma2(acc[r], sv.y, w1);
        }
    }
}

// ---------------- recurrent kernel: 512 threads, K split across 2 halves ----------------
__global__ void __launch_bounds__(512) rec_kernel(
    const int* __restrict__ x, const float* __restrict__ tt,
    const float* __restrict__ b_hh,
    const float* __restrict__ b1, const float* __restrict__ b2)
{
    extern __shared__ ull dynsmem[];
    __half2* sW1 = (__half2*)dynsmem;            // KC*H half2 (72 KB)
    __half2* sW2 = sW1 + KC * H;                 // 72 KB
    float* fbase = (float*)(sW2 + KC * H);
    float (*sh_h)[H] = (float (*)[H])fbase;                  // 8x256
    float (*sh_a)[H] = (float (*)[H])(fbase + BT * H);
    float (*sh_t)[H] = (float (*)[H])(fbase + 2 * BT * H);
    float* red = fbase + 3 * BT * H;                         // 2x3x8x256 floats (48 KB)
    int*   sh_it = (int*)(red + 2 * 3 * BT * H);
    float* sh_dt = (float*)(sh_it + BT);

    const int tid = threadIdx.x;
    const int j = tid & 255;
    const int half = tid >> 8;
    const int r0 = half * 4;                     // this thread's 4 rows
    const int b0 = blockIdx.x * BT;

#define RG(hh, g, r) ((((hh) * 3 + (g)) * 8 + (r)) * H + j)

    // cache KC k-pair slabs of W1/W2 in smem (fp16)
    for (int i = tid; i < KC * H; i += 512) { sW1[i] = g_W1H[i]; sW2[i] = g_W2H[i]; }

    const float bhhr = b_hh[j], bhhz = b_hh[H + j], bhhn = b_hh[2 * H + j];
    const float b1j = b1[j], b2j = b2[j];

#pragma unroll
    for (int q = 0; q < 4; q++) sh_h[r0 + q][j] = 0.f;
    float hnew[4];
#pragma unroll
    for (int q = 0; q < 4; q++) hnew[q] = 0.f;
    __syncthreads();

    const ull* __restrict__ whh = g_WhhP;

    for (int s = 0; s < S; s++) {
        if (tid < BT) {
            sh_it[tid] = x[(b0 + tid) * S + s];
            float tc = tt[(b0 + tid) * S + s];
            float d = 0.f;
            if (s < S - 1) {
                float tn = tt[(b0 + tid) * S + s + 1];
                d = fmaxf(tn, tc + 1e-5f) - tc;
            }
            sh_dt[tid] = d;
        }
        __syncthreads();   // (A)

        // issue long-latency Etab gathers early
        float giR[4], giZ[4], giN[4], dt4[4];
#pragma unroll
        for (int q = 0; q < 4; q++) {
            const float* e = g_Etab + (size_t)sh_it[r0 + q] * 768;
            giR[q] = e[j];
            giZ[q] = e[H + j];
            giN[q] = e[2 * H + j];
            dt4[q] = sh_dt[r0 + q];
        }

        // ---- GRU partial gate matmul over this half's 64 kp (fp32 weights) ----
        ull aR[BT], aZ[BT], aN[BT];
#pragma unroll
        for (int r = 0; r < BT; r++) { aR[r] = 0ull; aZ[r] = 0ull; aN[r] = 0ull; }

        const int kpb = half * 64;
#pragma unroll 2
        for (int p = 0; p < 32; p++) {
            const int kp = kpb + 2 * p;
            const ull* wp = whh + (size_t)kp * 768 + j;
            ull w0R = wp[0],   w0Z = wp[256],  w0N = wp[512];
            ull w1R = wp[768], w1Z = wp[1024], w1N = wp[1280];
#pragma unroll
            for (int r = 0; r < BT; r++) {
                ulonglong2 hv = *(const ulonglong2*)&sh_h[r][2 * kp];
                ffma2(aR[r], hv.x, w0R);
                ffma2(aZ[r], hv.x, w0Z);
                ffma2(aN[r], hv.x, w0N);
                ffma2(aR[r], hv.y, w1R);
                ffma2(aZ[r], hv.y, w1Z);
                ffma2(aN[r], hv.y, w1N);
            }
        }

        // write partials for the OTHER half's rows only
        {
            const int ro = (1 - half) * 4;
#pragma unroll
            for (int q = 0; q < 4; q++) {
                red[RG(half, 0, q * 2)] = hsum2(aR[ro + q]);
                red[RG(half, 1, q * 2)] = hsum2(aZ[ro + q]);
                red[RG(half, 2, q * 2)] = hsum2(aN[ro + q]);
            }
        }
        __syncthreads();

        // combine + GRU elementwise for this thread's 4 rows
#pragma unroll
        for (int q = 0; q < 4; q++) {
            int r = r0 + q;
            float pR = hsum2(aR[r]) + red[RG(1 - half, 0, q * 2)];
            float pZ = hsum2(aZ[r]) + red[RG(1 - half, 1, q * 2)];
            float pN = hsum2(aN[r]) + red[RG(1 - half, 2, q * 2)];
            float rg = sigm(giR[q] + pR + bhhr);
            float zg = sigm(giZ[q] + pZ + bhhz);
            float ng = ftanh(giN[q] + rg * (pN + bhhn));
            float hold = sh_h[r][j];
            hnew[q] = (1.f - zg) * ng + zg * hold;
        }
        __syncthreads();
#pragma unroll
        for (int q = 0; q < 4; q++) sh_h[r0 + q][j] = hnew[q];
        __syncthreads();

        // ---- RK4 ----
        float ksum[4], kv[4];
        ull acc[BT];
        float (*src)[H] = sh_h;

#pragma unroll 1
        for (int eval = 0; eval < 4; eval++) {
            // layer 1
            mm_partial(src, sW1, g_W1H, j, half, acc);
            {
                const int ro = (1 - half) * 4;
#pragma unroll
                for (int q = 0; q < 4; q++) red[RG(half, 0, q * 2)] = hsum2(acc[ro + q]);
            }
            __syncthreads();
#pragma unroll
            for (int q = 0; q < 4; q++) {
                int r = r0 + q;
                sh_a[r][j] = ftanh(hsum2(acc[r]) + red[RG(1 - half, 0, q * 2)] + b1j);
            }
            __syncthreads();

            // layer 2
            mm_partial(sh_a, sW2, g_W2H, j, half, acc);
            {
                const int ro = (1 - half) * 4;
#pragma unroll
                for (int q = 0; q < 4; q++) red[RG(half, 0, q * 2)] = hsum2(acc[ro + q]);
            }
            __syncthreads();
#pragma unroll
            for (int q = 0; q < 4; q++) {
                kv[q] = hsum2(acc[r0 + q]) + red[RG(1 - half, 0, q * 2)] + b2j;
            }

            if (eval == 0) {
#pragma unroll
                for (int q = 0; q < 4; q++) {
                    ksum[q] = kv[q];
                    sh_t[r0 + q][j] = hnew[q] + 0.5f * dt4[q] * kv[q];
                }
            } else if (eval == 1) {
#pragma unroll
                for (int q = 0; q < 4; q++) {
                    ksum[q] += 2.f * kv[q];
                    sh_t[r0 + q][j] = hnew[q] + 0.5f * dt4[q] * kv[q];
                }
            } else if (eval == 2) {
#pragma unroll
                for (int q = 0; q < 4; q++) {
                    ksum[q] += 2.f * kv[q];
                    sh_t[r0 + q][j] = hnew[q] + dt4[q] * kv[q];
                }
            } else {
#pragma unroll
                for (int q = 0; q < 4; q++) {
                    ksum[q] += kv[q];
                    hnew[q] = hnew[q] + (dt4[q] * (1.f / 6.f)) * ksum[q];
                    sh_h[r0 + q][j] = hnew[q];
                }
            }
            __syncthreads();
            src = sh_t;
        }
    }

#pragma unroll
    for (int q = 0; q < 4; q++) g_hfin[(b0 + r0 + q) * H + j] = hnew[q];
#undef RG
}

// ---------------- launch ----------------
extern "C" void kernel_launch(void* const* d_in, const int* in_sizes, int n_in,
                              void* d_out, int out_size)
{
    const int*   x      = (const int*)d_in[0];
    const float* t      = (const float*)d_in[1];
    const float* emb    = (const float*)d_in[2];
    const float* W_ih   = (const float*)d_in[3];
    const float* W_hh   = (const float*)d_in[4];
    const float* b_ih   = (const float*)d_in[5];
    const float* b_hh   = (const float*)d_in[6];
    const float* W1     = (const float*)d_in[7];
    const float* b1     = (const float*)d_in[8];
    const float* W2     = (const float*)d_in[9];
    const float* b2     = (const float*)d_in[10];
    const float* W_head = (const float*)d_in[11];
    const float* b_head = (const float*)d_in[12];
    float* out = (float*)d_out;

    float* etab_ptr = nullptr;
    float* hfin_ptr = nullptr;
    cudaGetSymbolAddress((void**)&etab_ptr, g_Etab);
    cudaGetSymbolAddress((void**)&hfin_ptr, g_hfin);

    const int smem_bytes = 2 * KC * H * (int)sizeof(__half2)        // fp16 W1/W2 cache (144 KB)
                         + 3 * BT * H * (int)sizeof(float)          // h/a/t (24 KB)
                         + 2 * 3 * BT * H * (int)sizeof(float)      // reduction buffer (48 KB)
                         + BT * (int)(sizeof(int) + sizeof(float));
    cudaFuncSetAttribute(rec_kernel, cudaFuncAttributeMaxDynamicSharedMemorySize, smem_bytes);

    prep_pack<<<(128 * 768 + 255) / 256, 256>>>(W_hh, W1, W2);

    // Etab = item_emb @ W_ih^T + b_ih   [50000, 768]
    dim3 ge(768 / GN, (NITEMS + GM - 1) / GM);
    gemm_nt<<<ge, 256>>>(emb, W_ih, b_ih, etab_ptr, NITEMS, 768);

    rec_kernel<<<BSZ / BT, 512, smem_bytes>>>(x, t, b_hh, b1, b2);

    // out = h_fin @ W_head^T + b_head   [1024, 50000]
    dim3 gh((NITEMS + GN - 1) / GN, BSZ / GM);
    gemm_nt<<<gh, 256>>>(hfin_ptr, W_head, b_head, out, BSZ, NITEMS);
}